// round 15
// baseline (speedup 1.0000x reference)
#include <cuda_runtime.h>
#include <cuda_fp16.h>

#define BATCH   65536
#define NPLAYER 3
#define OBSD    48
#define TB      32
#define THREADS 256

// pitches in 32-bit words (all %32==4 -> conflict-free LDS/LDSM phases)
#define PHIDW 196   // hid fp16: 192 words (384 halves)
#define PE16W 292   // enc fp16: 288 words (576 halves)
#define PH1W  132   // h1/h2 fp16: 128 words (256 halves)

// smem word offsets (lifetime-overlapped)
#define HID_OFF  0
#define EF16_OFF 6272
#define SMEM_WORDS 15616

// packed fp16 weights (float4 = 4 x b32, each b32 = half2 (k,k+1))
#define PKP_ENC 0
#define PKP_PI1 7680
#define PKP_PI2 26112
#define PKP_PI3 34304
#define PK_PLAYER 34560
#define PK_TOTAL (3 * PK_PLAYER)

__device__ float4 g_pk4[PK_TOTAL];

__device__ __forceinline__ float lrelu(float x) { return fmaxf(x, 0.01f * x); }

__device__ __forceinline__ unsigned pack_h2(float a, float b) {
    __half2 h = __floats2half2_rn(a, b);
    return *reinterpret_cast<unsigned*>(&h);
}

__device__ __forceinline__ unsigned s2u(const void* p) {
    return (unsigned)__cvta_generic_to_shared(p);
}

#define LDSM4(a, addr) \
    asm volatile("ldmatrix.sync.aligned.m8n8.x4.shared.b16 {%0,%1,%2,%3}, [%4];" \
        : "=r"((a)[0]), "=r"((a)[1]), "=r"((a)[2]), "=r"((a)[3]) : "r"(addr))

__device__ __forceinline__ void mma_f16(float d[4], const unsigned a[4],
                                        unsigned b0, unsigned b1) {
    asm volatile(
        "mma.sync.aligned.m16n8k16.row.col.f32.f16.f16.f32 "
        "{%0,%1,%2,%3}, {%4,%5,%6,%7}, {%8,%9}, {%0,%1,%2,%3};"
        : "+f"(d[0]), "+f"(d[1]), "+f"(d[2]), "+f"(d[3])
        : "r"(a[0]), "r"(a[1]), "r"(a[2]), "r"(a[3]), "r"(b0), "r"(b1));
}

// =================== repack: fp16 fragment-order weights (unchanged) ===================
__global__ void repack_kernel(const float* __restrict__ prop_W2,
                              const float* __restrict__ ext_W2,
                              const float* __restrict__ opp_W2,
                              const float* __restrict__ pi_W1,
                              const float* __restrict__ pi_W2,
                              const float* __restrict__ pi_W3) {
    int idx = blockIdx.x * 256 + threadIdx.x;
    if (idx >= PK_TOTAL) return;
    int p = idx / PK_PLAYER;
    int r = idx - p * PK_PLAYER;
    unsigned o[4];
    if (r < PKP_PI1) {
        int pass = r / 2560, e = r - pass * 2560;
        int warp = e / 320, e2 = e - warp * 320;
        int c = e2 / 160, e3 = e2 - c * 160;
        int t = e3 >> 5, lane = e3 & 31;
        int gr = lane >> 2, gc = lane & 3;
        #pragma unroll
        for (int q = 0; q < 4; q++) {
            int j = t * 2 + (q >> 1), b = q & 1;
            if (j > 8) { o[q] = 0; continue; }
            int col = warp * 72 + j * 8 + gr;
            int k = c * 16 + 2 * gc + b * 8;
            float w0, w1;
            if (pass == 0) {
                int head = col >> 6, cc = col & 63;
                const float* W = prop_W2 + ((size_t)(p * 9 + head) * 32) * 64 + cc;
                w0 = W[(size_t)k * 64]; w1 = W[(size_t)(k + 1) * 64];
            } else if (pass == 1) {
                int head = (col >= 288) ? 1 : 0, cc = col - head * 288;
                const float* W = ext_W2 + ((size_t)(p * 2 + head) * 32) * 288 + cc;
                w0 = W[(size_t)k * 288]; w1 = W[(size_t)(k + 1) * 288];
            } else {
                const float* W = opp_W2 + ((size_t)p * 32) * 576 + col;
                w0 = W[(size_t)k * 576]; w1 = W[(size_t)(k + 1) * 576];
            }
            o[q] = pack_h2(w0, w1);
        }
    } else if (r < PKP_PI3) {
        int base;
        const float* W;
        if (r < PKP_PI2) { base = r - PKP_PI1; W = pi_W1 + (size_t)p * 147456; }
        else             { base = r - PKP_PI2; W = pi_W2 + (size_t)p * 65536; }
        int c = base / 512, e2 = base - c * 512;
        int nw = e2 >> 6, e3 = e2 & 63;
        int jp = e3 >> 5, lane = e3 & 31;
        int gr = lane >> 2, gc = lane & 3;
        #pragma unroll
        for (int q = 0; q < 4; q++) {
            int j = jp * 2 + (q >> 1), b = q & 1;
            int k = c * 16 + 2 * gc + b * 8;
            int n = nw * 32 + j * 8 + gr;
            o[q] = pack_h2(W[(size_t)k * 256 + n], W[(size_t)(k + 1) * 256 + n]);
        }
    } else {
        int e = r - PKP_PI3;
        int cp = e >> 5, lane = e & 31;
        int gr = lane >> 2, gc = lane & 3;
        const float* W = pi_W3 + (size_t)p * 768;
        #pragma unroll
        for (int q = 0; q < 4; q++) {
            int c = cp * 2 + (q >> 1), b = q & 1;
            int k = c * 16 + 2 * gc + b * 8;
            float w0 = 0.f, w1 = 0.f;
            if (gr < 3) { w0 = W[(size_t)k * 3 + gr]; w1 = W[(size_t)(k + 1) * 3 + gr]; }
            o[q] = pack_h2(w0, w1);
        }
    }
    g_pk4[idx] = make_float4(__uint_as_float(o[0]), __uint_as_float(o[1]),
                             __uint_as_float(o[2]), __uint_as_float(o[3]));
}

// =================== stage-1b fused: ext/opp A hoisted (branch-free), prop per-j ===================
__device__ __forceinline__ void enc_all(const float* __restrict__ prop_b2,
                                        const float* __restrict__ ext_b2,
                                        const float* __restrict__ opp_b2,
                                        float* ef16,
                                        unsigned aad0, unsigned aad1,
                                        int warp, int lane, int p) {
    const int gr = lane >> 2, gc = lane & 3;
    const int cw = warp * 72;
    const float4* pk = g_pk4 + (size_t)p * PK_PLAYER + PKP_ENC + warp * 320 + lane;

    // hoisted A fragments: ext (head fixed per warp) and opp (single head)
    unsigned af1[2][2][4], af2[2][2][4];
    const int h1 = (cw >= 288) ? 1 : 0;
    {
        unsigned ab1 = (unsigned)(144 + h1 * 16) * 4;
        unsigned ab2 = 176u * 4;
        #pragma unroll
        for (int c = 0; c < 2; c++) {
            LDSM4(af1[c][0], aad0 + ab1 + c * 32);
            LDSM4(af1[c][1], aad1 + ab1 + c * 32);
            LDSM4(af2[c][0], aad0 + ab2 + c * 32);
            LDSM4(af2[c][1], aad1 + ab2 + c * 32);
        }
    }

    #pragma unroll
    for (int j = 0; j < 9; j++) {
        const int c0 = cw + j * 8;
        const int cb = c0 + 2 * gc;
        const int h0 = c0 >> 6;
        float sum[2][4];
        #pragma unroll
        for (int m = 0; m < 2; m++)
            #pragma unroll
            for (int u = 0; u < 4; u++) sum[m][u] = 0.f;

        // pass 0: prop (A loaded per j, unconditional -> no branches)
        {
            float acc[2][4] = {{0.f,0.f,0.f,0.f},{0.f,0.f,0.f,0.f}};
            unsigned ab = (unsigned)(h0 * 16) * 4;
            #pragma unroll
            for (int c = 0; c < 2; c++) {
                unsigned a0[4], a1[4];
                LDSM4(a0, aad0 + ab + c * 32);
                LDSM4(a1, aad1 + ab + c * 32);
                float4 v = pk[c * 160 + (j >> 1) * 32];
                unsigned b0 = __float_as_uint((j & 1) ? v.z : v.x);
                unsigned b1 = __float_as_uint((j & 1) ? v.w : v.y);
                mma_f16(acc[0], a0, b0, b1);
                mma_f16(acc[1], a1, b0, b1);
            }
            float b0f = prop_b2[(p * 9 + h0) * 64 + (cb & 63)];
            float b1f = prop_b2[(p * 9 + h0) * 64 + (cb & 63) + 1];
            #pragma unroll
            for (int m = 0; m < 2; m++) {
                sum[m][0] += lrelu(acc[m][0] + b0f);
                sum[m][1] += lrelu(acc[m][1] + b1f);
                sum[m][2] += lrelu(acc[m][2] + b0f);
                sum[m][3] += lrelu(acc[m][3] + b1f);
            }
        }
        // pass 1: ext (hoisted A)
        {
            float acc[2][4] = {{0.f,0.f,0.f,0.f},{0.f,0.f,0.f,0.f}};
            #pragma unroll
            for (int c = 0; c < 2; c++) {
                float4 v = pk[2560 + c * 160 + (j >> 1) * 32];
                unsigned b0 = __float_as_uint((j & 1) ? v.z : v.x);
                unsigned b1 = __float_as_uint((j & 1) ? v.w : v.y);
                mma_f16(acc[0], af1[c][0], b0, b1);
                mma_f16(acc[1], af1[c][1], b0, b1);
            }
            int bidx = (p * 2 + h1) * 288 + cb - h1 * 288;
            float b0f = ext_b2[bidx], b1f = ext_b2[bidx + 1];
            #pragma unroll
            for (int m = 0; m < 2; m++) {
                sum[m][0] += lrelu(acc[m][0] + b0f);
                sum[m][1] += lrelu(acc[m][1] + b1f);
                sum[m][2] += lrelu(acc[m][2] + b0f);
                sum[m][3] += lrelu(acc[m][3] + b1f);
            }
        }
        // pass 2: opp (hoisted A)
        {
            float acc[2][4] = {{0.f,0.f,0.f,0.f},{0.f,0.f,0.f,0.f}};
            #pragma unroll
            for (int c = 0; c < 2; c++) {
                float4 v = pk[2 * 2560 + c * 160 + (j >> 1) * 32];
                unsigned b0 = __float_as_uint((j & 1) ? v.z : v.x);
                unsigned b1 = __float_as_uint((j & 1) ? v.w : v.y);
                mma_f16(acc[0], af2[c][0], b0, b1);
                mma_f16(acc[1], af2[c][1], b0, b1);
            }
            float b0f = opp_b2[p * 576 + cb], b1f = opp_b2[p * 576 + cb + 1];
            #pragma unroll
            for (int m = 0; m < 2; m++) {
                sum[m][0] += lrelu(acc[m][0] + b0f);
                sum[m][1] += lrelu(acc[m][1] + b1f);
                sum[m][2] += lrelu(acc[m][2] + b0f);
                sum[m][3] += lrelu(acc[m][3] + b1f);
            }
        }
        const int wc = (c0 >> 1) + gc;
        #pragma unroll
        for (int m = 0; m < 2; m++) {
            int rr = m * 16 + gr;
            ef16[(rr    ) * PE16W + wc] = __uint_as_float(pack_h2(sum[m][0], sum[m][1]));
            ef16[(rr + 8) * PE16W + wc] = __uint_as_float(pack_h2(sum[m][2], sum[m][3]));
        }
    }
}

// =================== pi GEMM: 8 n-warps, full K, LDSM A, depth-2 B prefetch ===================
template<int NCH, int PKOFF, int PAW>
__device__ __forceinline__ void pi_stage(const float* __restrict__ bias,
                                         const float* sAw, float* outp, int outPitch,
                                         int warp, int lane, int p) {
    const int n0 = warp * 32;
    const int gr = lane >> 2, gc = lane & 3;
    const float4* pk = g_pk4 + (size_t)p * PK_PLAYER + PKOFF + warp * 64 + lane;
    const unsigned aad0 = s2u(sAw + (lane & 15) * PAW + ((lane >> 4) << 2));
    const unsigned aad1 = s2u(sAw + (16 + (lane & 15)) * PAW + ((lane >> 4) << 2));

    float acc[2][4][4];
    #pragma unroll
    for (int m = 0; m < 2; m++)
        #pragma unroll
        for (int j = 0; j < 4; j++)
            #pragma unroll
            for (int u = 0; u < 4; u++) acc[m][j][u] = 0.f;

    float4 b0r[2], b1r[2];
    b0r[0] = pk[0];   b1r[0] = pk[32];
    b0r[1] = pk[512]; b1r[1] = pk[512 + 32];

    #pragma unroll 4
    for (int c = 0; c < NCH; c++) {
        float4 v0 = b0r[c & 1], v1 = b1r[c & 1];
        if (c + 2 < NCH) {
            b0r[c & 1] = pk[(c + 2) * 512];
            b1r[c & 1] = pk[(c + 2) * 512 + 32];
        }
        unsigned a0[4], a1[4];
        LDSM4(a0, aad0 + c * 32);
        LDSM4(a1, aad1 + c * 32);
        mma_f16(acc[0][0], a0, __float_as_uint(v0.x), __float_as_uint(v0.y));
        mma_f16(acc[0][1], a0, __float_as_uint(v0.z), __float_as_uint(v0.w));
        mma_f16(acc[0][2], a0, __float_as_uint(v1.x), __float_as_uint(v1.y));
        mma_f16(acc[0][3], a0, __float_as_uint(v1.z), __float_as_uint(v1.w));
        mma_f16(acc[1][0], a1, __float_as_uint(v0.x), __float_as_uint(v0.y));
        mma_f16(acc[1][1], a1, __float_as_uint(v0.z), __float_as_uint(v0.w));
        mma_f16(acc[1][2], a1, __float_as_uint(v1.x), __float_as_uint(v1.y));
        mma_f16(acc[1][3], a1, __float_as_uint(v1.z), __float_as_uint(v1.w));
    }

    #pragma unroll
    for (int m = 0; m < 2; m++) {
        int rr = m * 16 + gr;
        #pragma unroll
        for (int j = 0; j < 4; j++) {
            int cA = n0 + j * 8 + 2 * gc;
            float b0 = bias[cA], b1 = bias[cA + 1];
            float v00 = lrelu(acc[m][j][0] + b0), v01 = lrelu(acc[m][j][1] + b1);
            float v10 = lrelu(acc[m][j][2] + b0), v11 = lrelu(acc[m][j][3] + b1);
            int wc = cA >> 1;
            outp[(rr    ) * outPitch + wc] = __uint_as_float(pack_h2(v00, v01));
            outp[(rr + 8) * outPitch + wc] = __uint_as_float(pack_h2(v10, v11));
        }
    }
}

__global__ __launch_bounds__(THREADS, 3)
void mlpac_kernel(
    const float* __restrict__ obs,
    const float* __restrict__ prop_W1, const float* __restrict__ prop_b1,
    const float* __restrict__ prop_b2,
    const float* __restrict__ ext_W1,  const float* __restrict__ ext_b1,
    const float* __restrict__ ext_b2,
    const float* __restrict__ opp_W1,  const float* __restrict__ opp_b1,
    const float* __restrict__ opp_b2,
    const float* __restrict__ pi_b1,   const float* __restrict__ pi_b2,
    const float* __restrict__ pi_b3,
    float* __restrict__ out)
{
    extern __shared__ float sm[];
    float* s_hid  = sm + HID_OFF;
    float* s_ef16 = sm + EF16_OFF;
    float* s_obs  = s_ef16;
    float* s_h1   = sm + HID_OFF;
    float* s_h2   = sm + EF16_OFF;

    const int tid  = threadIdx.x;
    const int warp = tid >> 5, lane = tid & 31;
    const int p    = blockIdx.y;
    const int b0   = blockIdx.x * TB;

    // ---------------- stage 0: obs ----------------
    for (int g = tid; g < TB * (OBSD / 4); g += THREADS) {
        int r = g / 12, q = g - r * 12;
        *(float4*)&s_obs[r * PE16W + q * 4] =
            *(const float4*)&obs[((size_t)(b0 + r) * NPLAYER + p) * OBSD + q * 4];
    }
    __syncthreads();

    // ---------------- stage 1a: hidden layers -> fp16 words ----------------
    // prop: division-free mapping: thread = (row r = tid>>3, slot t8 = tid&7), 18 cols each
    {
        const int r = tid >> 3, t8 = tid & 7;
        const float* orow = &s_obs[r * PE16W];
        #pragma unroll
        for (int it = 0; it < 18; it++) {
            int col = t8 * 18 + it;          // 0..143
            int n = col >> 4, jw = col & 15;
            const float* w = prop_W1 + ((p * 9 + n) * 2) * 32 + 2 * jw;
            const float* bb = prop_b1 + (p * 9 + n) * 32 + 2 * jw;
            float o0 = orow[2 * n], o1 = orow[2 * n + 1];
            float v0 = lrelu(o0 * w[0] + o1 * w[32] + bb[0]);
            float v1 = lrelu(o0 * w[1] + o1 * w[33] + bb[1]);
            s_hid[r * PHIDW + n * 16 + jw] = __uint_as_float(pack_h2(v0, v1));
        }
    }
    for (int i = tid; i < 32 * 2 * 16; i += THREADS) {
        int r = i >> 5, rest = i & 31, n = rest >> 4, jw = rest & 15;
        const float* w = ext_W1 + ((p * 2 + n) * 6) * 32 + 2 * jw;
        const float* bb = ext_b1 + (p * 2 + n) * 32 + 2 * jw;
        float v0 = bb[0], v1 = bb[1];
        #pragma unroll
        for (int q = 0; q < 6; q++) {
            float o = s_obs[r * PE16W + 18 + n * 6 + q];
            v0 += o * w[q * 32]; v1 += o * w[q * 32 + 1];
        }
        s_hid[r * PHIDW + 144 + n * 16 + jw] = __uint_as_float(pack_h2(lrelu(v0), lrelu(v1)));
    }
    for (int i = tid; i < 32 * 16; i += THREADS) {
        int r = i >> 4, jw = i & 15;
        const float* w = opp_W1 + (p * 18) * 32 + 2 * jw;
        const float* bb = opp_b1 + p * 32 + 2 * jw;
        float v0 = bb[0], v1 = bb[1];
        #pragma unroll
        for (int q = 0; q < 18; q++) {
            float o = s_obs[r * PE16W + 30 + q];
            v0 += o * w[q * 32]; v1 += o * w[q * 32 + 1];
        }
        s_hid[r * PHIDW + 176 + jw] = __uint_as_float(pack_h2(lrelu(v0), lrelu(v1)));
    }
    __syncthreads();

    // ---------------- stage 1b: enc (fused; ext/opp hoisted) ----------------
    {
        unsigned aad0 = s2u(s_hid + (lane & 15) * PHIDW + ((lane >> 4) << 2));
        unsigned aad1 = s2u(s_hid + (16 + (lane & 15)) * PHIDW + ((lane >> 4) << 2));
        enc_all(prop_b2, ext_b2, opp_b2, s_ef16, aad0, aad1, warp, lane, p);
    }
    __syncthreads();

    // ---------------- stage 2: h1 = lrelu(enc @ pi_W1 + b1) ----------------
    pi_stage<36, PKP_PI1, PE16W>(pi_b1 + p * 256, s_ef16, s_h1, PH1W, warp, lane, p);
    __syncthreads();

    // ---------------- stage 3: h2 = lrelu(h1 @ pi_W2 + b2) ----------------
    pi_stage<16, PKP_PI2, PH1W>(pi_b2 + p * 256, s_h1, s_h2, PH1W, warp, lane, p);
    __syncthreads();

    // ---------------- stage 4: out = tanh(h2 @ pi_W3 + b3)  [1 warp, mma] ----------------
    if (warp == 0) {
        const int gr = lane >> 2, gc = lane & 3;
        const float4* pkw3 = g_pk4 + (size_t)p * PK_PLAYER + PKP_PI3;
        const unsigned aad0 = s2u(s_h2 + (lane & 15) * PH1W + ((lane >> 4) << 2));
        const unsigned aad1 = s2u(s_h2 + (16 + (lane & 15)) * PH1W + ((lane >> 4) << 2));
        float acc[2][4];
        #pragma unroll
        for (int m = 0; m < 2; m++)
            #pragma unroll
            for (int u = 0; u < 4; u++) acc[m][u] = 0.f;
        #pragma unroll
        for (int c = 0; c < 16; c++) {
            float4 v = pkw3[(c >> 1) * 32 + lane];
            unsigned b0 = __float_as_uint((c & 1) ? v.z : v.x);
            unsigned b1 = __float_as_uint((c & 1) ? v.w : v.y);
            unsigned a0[4], a1[4];
            LDSM4(a0, aad0 + c * 32);
            LDSM4(a1, aad1 + c * 32);
            mma_f16(acc[0], a0, b0, b1);
            mma_f16(acc[1], a1, b0, b1);
        }
        int c0 = 2 * gc, c1 = 2 * gc + 1;
        float bb0 = (c0 < 3) ? pi_b3[p * 3 + c0] : 0.f;
        float bb1 = (c1 < 3) ? pi_b3[p * 3 + c1] : 0.f;
        #pragma unroll
        for (int m = 0; m < 2; m++) {
            int r0 = m * 16 + gr, r1 = r0 + 8;
            if (c0 < 3) {
                out[((size_t)(b0 + r0) * NPLAYER + p) * 3 + c0] = tanhf(acc[m][0] + bb0);
                out[((size_t)(b0 + r1) * NPLAYER + p) * 3 + c0] = tanhf(acc[m][2] + bb0);
            }
            if (c1 < 3) {
                out[((size_t)(b0 + r0) * NPLAYER + p) * 3 + c1] = tanhf(acc[m][1] + bb1);
                out[((size_t)(b0 + r1) * NPLAYER + p) * 3 + c1] = tanhf(acc[m][3] + bb1);
            }
        }
    }
}

extern "C" void kernel_launch(void* const* d_in, const int* in_sizes, int n_in,
                              void* d_out, int out_size)
{
    (void)in_sizes; (void)n_in; (void)out_size;
    const float* obs     = (const float*)d_in[0];
    const float* prop_W1 = (const float*)d_in[1];
    const float* prop_b1 = (const float*)d_in[2];
    const float* prop_W2 = (const float*)d_in[3];
    const float* prop_b2 = (const float*)d_in[4];
    const float* ext_W1  = (const float*)d_in[5];
    const float* ext_b1  = (const float*)d_in[6];
    const float* ext_W2  = (const float*)d_in[7];
    const float* ext_b2  = (const float*)d_in[8];
    const float* opp_W1  = (const float*)d_in[9];
    const float* opp_b1  = (const float*)d_in[10];
    const float* opp_W2  = (const float*)d_in[11];
    const float* opp_b2  = (const float*)d_in[12];
    const float* pi_W1   = (const float*)d_in[13];
    const float* pi_b1   = (const float*)d_in[14];
    const float* pi_W2   = (const float*)d_in[15];
    const float* pi_b2   = (const float*)d_in[16];
    const float* pi_W3   = (const float*)d_in[17];
    const float* pi_b3   = (const float*)d_in[18];
    float* out = (float*)d_out;

    repack_kernel<<<(PK_TOTAL + 255) / 256, 256>>>(prop_W2, ext_W2, opp_W2,
                                                   pi_W1, pi_W2, pi_W3);

    const int smem_bytes = SMEM_WORDS * sizeof(float);
    cudaFuncSetAttribute(mlpac_kernel, cudaFuncAttributeMaxDynamicSharedMemorySize, smem_bytes);

    dim3 grid(BATCH / TB, NPLAYER);
    mlpac_kernel<<<grid, THREADS, smem_bytes>>>(
        obs, prop_W1, prop_b1, prop_b2,
        ext_W1, ext_b1, ext_b2,
        opp_W1, opp_b1, opp_b2,
        pi_b1, pi_b2, pi_b3, out);
}

// round 16
// speedup vs baseline: 1.5865x; 1.5865x over previous
#include <cuda_runtime.h>
#include <cuda_fp16.h>

#define BATCH   65536
#define NPLAYER 3
#define OBSD    48
#define TB      32
#define THREADS 256

// pitches in 32-bit words (all %32==4 -> conflict-free LDS/LDSM phases)
#define PHIDW 196   // hid fp16: 192 words (384 halves)
#define PE16W 292   // enc fp16: 288 words (576 halves)
#define PH1W  132   // h1/h2 fp16: 128 words (256 halves)

// smem word offsets (lifetime-overlapped)
#define HID_OFF  0
#define EF16_OFF 6272
#define SMEM_WORDS 15616

// packed fp16 weights (float4 = 4 x b32, each b32 = half2 (k,k+1))
#define PKP_ENC 0
#define PKP_PI1 7680
#define PKP_PI2 26112
#define PKP_PI3 34304
#define PK_PLAYER 34560
#define PK_TOTAL (3 * PK_PLAYER)

__device__ float4 g_pk4[PK_TOTAL];

__device__ __forceinline__ float lrelu(float x) { return fmaxf(x, 0.01f * x); }

__device__ __forceinline__ unsigned pack_h2(float a, float b) {
    __half2 h = __floats2half2_rn(a, b);
    return *reinterpret_cast<unsigned*>(&h);
}

__device__ __forceinline__ unsigned s2u(const void* p) {
    return (unsigned)__cvta_generic_to_shared(p);
}

#define LDSM4(a, addr) \
    asm volatile("ldmatrix.sync.aligned.m8n8.x4.shared.b16 {%0,%1,%2,%3}, [%4];" \
        : "=r"((a)[0]), "=r"((a)[1]), "=r"((a)[2]), "=r"((a)[3]) : "r"(addr))

__device__ __forceinline__ void mma_f16(float d[4], const unsigned a[4],
                                        unsigned b0, unsigned b1) {
    asm volatile(
        "mma.sync.aligned.m16n8k16.row.col.f32.f16.f16.f32 "
        "{%0,%1,%2,%3}, {%4,%5,%6,%7}, {%8,%9}, {%0,%1,%2,%3};"
        : "+f"(d[0]), "+f"(d[1]), "+f"(d[2]), "+f"(d[3])
        : "r"(a[0]), "r"(a[1]), "r"(a[2]), "r"(a[3]), "r"(b0), "r"(b1));
}

// =================== repack: fp16 fragment-order weights (unchanged) ===================
__global__ void repack_kernel(const float* __restrict__ prop_W2,
                              const float* __restrict__ ext_W2,
                              const float* __restrict__ opp_W2,
                              const float* __restrict__ pi_W1,
                              const float* __restrict__ pi_W2,
                              const float* __restrict__ pi_W3) {
    int idx = blockIdx.x * 256 + threadIdx.x;
    if (idx >= PK_TOTAL) return;
    int p = idx / PK_PLAYER;
    int r = idx - p * PK_PLAYER;
    unsigned o[4];
    if (r < PKP_PI1) {
        int pass = r / 2560, e = r - pass * 2560;
        int warp = e / 320, e2 = e - warp * 320;
        int c = e2 / 160, e3 = e2 - c * 160;
        int t = e3 >> 5, lane = e3 & 31;
        int gr = lane >> 2, gc = lane & 3;
        #pragma unroll
        for (int q = 0; q < 4; q++) {
            int j = t * 2 + (q >> 1), b = q & 1;
            if (j > 8) { o[q] = 0; continue; }
            int col = warp * 72 + j * 8 + gr;
            int k = c * 16 + 2 * gc + b * 8;
            float w0, w1;
            if (pass == 0) {
                int head = col >> 6, cc = col & 63;
                const float* W = prop_W2 + ((size_t)(p * 9 + head) * 32) * 64 + cc;
                w0 = W[(size_t)k * 64]; w1 = W[(size_t)(k + 1) * 64];
            } else if (pass == 1) {
                int head = (col >= 288) ? 1 : 0, cc = col - head * 288;
                const float* W = ext_W2 + ((size_t)(p * 2 + head) * 32) * 288 + cc;
                w0 = W[(size_t)k * 288]; w1 = W[(size_t)(k + 1) * 288];
            } else {
                const float* W = opp_W2 + ((size_t)p * 32) * 576 + col;
                w0 = W[(size_t)k * 576]; w1 = W[(size_t)(k + 1) * 576];
            }
            o[q] = pack_h2(w0, w1);
        }
    } else if (r < PKP_PI3) {
        int base;
        const float* W;
        if (r < PKP_PI2) { base = r - PKP_PI1; W = pi_W1 + (size_t)p * 147456; }
        else             { base = r - PKP_PI2; W = pi_W2 + (size_t)p * 65536; }
        int c = base / 512, e2 = base - c * 512;
        int nw = e2 >> 6, e3 = e2 & 63;
        int jp = e3 >> 5, lane = e3 & 31;
        int gr = lane >> 2, gc = lane & 3;
        #pragma unroll
        for (int q = 0; q < 4; q++) {
            int j = jp * 2 + (q >> 1), b = q & 1;
            int k = c * 16 + 2 * gc + b * 8;
            int n = nw * 32 + j * 8 + gr;
            o[q] = pack_h2(W[(size_t)k * 256 + n], W[(size_t)(k + 1) * 256 + n]);
        }
    } else {
        int e = r - PKP_PI3;
        int cp = e >> 5, lane = e & 31;
        int gr = lane >> 2, gc = lane & 3;
        const float* W = pi_W3 + (size_t)p * 768;
        #pragma unroll
        for (int q = 0; q < 4; q++) {
            int c = cp * 2 + (q >> 1), b = q & 1;
            int k = c * 16 + 2 * gc + b * 8;
            float w0 = 0.f, w1 = 0.f;
            if (gr < 3) { w0 = W[(size_t)k * 3 + gr]; w1 = W[(size_t)(k + 1) * 3 + gr]; }
            o[q] = pack_h2(w0, w1);
        }
    }
    g_pk4[idx] = make_float4(__uint_as_float(o[0]), __uint_as_float(o[1]),
                             __uint_as_float(o[2]), __uint_as_float(o[3]));
}

// =================== stage-1b fused: ext/opp A hoisted (branch-free), prop per-j ===================
__device__ __forceinline__ void enc_all(const float* __restrict__ prop_b2,
                                        const float* __restrict__ ext_b2,
                                        const float* __restrict__ opp_b2,
                                        float* ef16,
                                        unsigned aad0, unsigned aad1,
                                        int warp, int lane, int p) {
    const int gr = lane >> 2, gc = lane & 3;
    const int cw = warp * 72;
    const float4* pk = g_pk4 + (size_t)p * PK_PLAYER + PKP_ENC + warp * 320 + lane;

    // hoisted A fragments: ext (head fixed per warp) and opp (single head)
    unsigned af1[2][2][4], af2[2][2][4];
    const int h1 = (cw >= 288) ? 1 : 0;
    {
        unsigned ab1 = (unsigned)(144 + h1 * 16) * 4;
        unsigned ab2 = 176u * 4;
        #pragma unroll
        for (int c = 0; c < 2; c++) {
            LDSM4(af1[c][0], aad0 + ab1 + c * 32);
            LDSM4(af1[c][1], aad1 + ab1 + c * 32);
            LDSM4(af2[c][0], aad0 + ab2 + c * 32);
            LDSM4(af2[c][1], aad1 + ab2 + c * 32);
        }
    }

    #pragma unroll
    for (int j = 0; j < 9; j++) {
        const int c0 = cw + j * 8;
        const int cb = c0 + 2 * gc;
        const int h0 = c0 >> 6;
        float sum[2][4];
        #pragma unroll
        for (int m = 0; m < 2; m++)
            #pragma unroll
            for (int u = 0; u < 4; u++) sum[m][u] = 0.f;

        // pass 0: prop (A loaded per j, unconditional -> no branches)
        {
            float acc[2][4] = {{0.f,0.f,0.f,0.f},{0.f,0.f,0.f,0.f}};
            unsigned ab = (unsigned)(h0 * 16) * 4;
            #pragma unroll
            for (int c = 0; c < 2; c++) {
                unsigned a0[4], a1[4];
                LDSM4(a0, aad0 + ab + c * 32);
                LDSM4(a1, aad1 + ab + c * 32);
                float4 v = pk[c * 160 + (j >> 1) * 32];
                unsigned b0 = __float_as_uint((j & 1) ? v.z : v.x);
                unsigned b1 = __float_as_uint((j & 1) ? v.w : v.y);
                mma_f16(acc[0], a0, b0, b1);
                mma_f16(acc[1], a1, b0, b1);
            }
            float b0f = prop_b2[(p * 9 + h0) * 64 + (cb & 63)];
            float b1f = prop_b2[(p * 9 + h0) * 64 + (cb & 63) + 1];
            #pragma unroll
            for (int m = 0; m < 2; m++) {
                sum[m][0] += lrelu(acc[m][0] + b0f);
                sum[m][1] += lrelu(acc[m][1] + b1f);
                sum[m][2] += lrelu(acc[m][2] + b0f);
                sum[m][3] += lrelu(acc[m][3] + b1f);
            }
        }
        // pass 1: ext (hoisted A)
        {
            float acc[2][4] = {{0.f,0.f,0.f,0.f},{0.f,0.f,0.f,0.f}};
            #pragma unroll
            for (int c = 0; c < 2; c++) {
                float4 v = pk[2560 + c * 160 + (j >> 1) * 32];
                unsigned b0 = __float_as_uint((j & 1) ? v.z : v.x);
                unsigned b1 = __float_as_uint((j & 1) ? v.w : v.y);
                mma_f16(acc[0], af1[c][0], b0, b1);
                mma_f16(acc[1], af1[c][1], b0, b1);
            }
            int bidx = (p * 2 + h1) * 288 + cb - h1 * 288;
            float b0f = ext_b2[bidx], b1f = ext_b2[bidx + 1];
            #pragma unroll
            for (int m = 0; m < 2; m++) {
                sum[m][0] += lrelu(acc[m][0] + b0f);
                sum[m][1] += lrelu(acc[m][1] + b1f);
                sum[m][2] += lrelu(acc[m][2] + b0f);
                sum[m][3] += lrelu(acc[m][3] + b1f);
            }
        }
        // pass 2: opp (hoisted A)
        {
            float acc[2][4] = {{0.f,0.f,0.f,0.f},{0.f,0.f,0.f,0.f}};
            #pragma unroll
            for (int c = 0; c < 2; c++) {
                float4 v = pk[2 * 2560 + c * 160 + (j >> 1) * 32];
                unsigned b0 = __float_as_uint((j & 1) ? v.z : v.x);
                unsigned b1 = __float_as_uint((j & 1) ? v.w : v.y);
                mma_f16(acc[0], af2[c][0], b0, b1);
                mma_f16(acc[1], af2[c][1], b0, b1);
            }
            float b0f = opp_b2[p * 576 + cb], b1f = opp_b2[p * 576 + cb + 1];
            #pragma unroll
            for (int m = 0; m < 2; m++) {
                sum[m][0] += lrelu(acc[m][0] + b0f);
                sum[m][1] += lrelu(acc[m][1] + b1f);
                sum[m][2] += lrelu(acc[m][2] + b0f);
                sum[m][3] += lrelu(acc[m][3] + b1f);
            }
        }
        const int wc = (c0 >> 1) + gc;
        #pragma unroll
        for (int m = 0; m < 2; m++) {
            int rr = m * 16 + gr;
            ef16[(rr    ) * PE16W + wc] = __uint_as_float(pack_h2(sum[m][0], sum[m][1]));
            ef16[(rr + 8) * PE16W + wc] = __uint_as_float(pack_h2(sum[m][2], sum[m][3]));
        }
    }
}

// =================== pi GEMM: 8 n-warps, full K, LDSM A, depth-2 B prefetch ===================
template<int NCH, int PKOFF, int PAW>
__device__ __forceinline__ void pi_stage(const float* __restrict__ bias,
                                         const float* sAw, float* outp, int outPitch,
                                         int warp, int lane, int p) {
    const int n0 = warp * 32;
    const int gr = lane >> 2, gc = lane & 3;
    const float4* pk = g_pk4 + (size_t)p * PK_PLAYER + PKOFF + warp * 64 + lane;
    const unsigned aad0 = s2u(sAw + (lane & 15) * PAW + ((lane >> 4) << 2));
    const unsigned aad1 = s2u(sAw + (16 + (lane & 15)) * PAW + ((lane >> 4) << 2));

    float acc[2][4][4];
    #pragma unroll
    for (int m = 0; m < 2; m++)
        #pragma unroll
        for (int j = 0; j < 4; j++)
            #pragma unroll
            for (int u = 0; u < 4; u++) acc[m][j][u] = 0.f;

    float4 b0r[2], b1r[2];
    b0r[0] = pk[0];   b1r[0] = pk[32];
    b0r[1] = pk[512]; b1r[1] = pk[512 + 32];

    #pragma unroll 4
    for (int c = 0; c < NCH; c++) {
        float4 v0 = b0r[c & 1], v1 = b1r[c & 1];
        if (c + 2 < NCH) {
            b0r[c & 1] = pk[(c + 2) * 512];
            b1r[c & 1] = pk[(c + 2) * 512 + 32];
        }
        unsigned a0[4], a1[4];
        LDSM4(a0, aad0 + c * 32);
        LDSM4(a1, aad1 + c * 32);
        mma_f16(acc[0][0], a0, __float_as_uint(v0.x), __float_as_uint(v0.y));
        mma_f16(acc[0][1], a0, __float_as_uint(v0.z), __float_as_uint(v0.w));
        mma_f16(acc[0][2], a0, __float_as_uint(v1.x), __float_as_uint(v1.y));
        mma_f16(acc[0][3], a0, __float_as_uint(v1.z), __float_as_uint(v1.w));
        mma_f16(acc[1][0], a1, __float_as_uint(v0.x), __float_as_uint(v0.y));
        mma_f16(acc[1][1], a1, __float_as_uint(v0.z), __float_as_uint(v0.w));
        mma_f16(acc[1][2], a1, __float_as_uint(v1.x), __float_as_uint(v1.y));
        mma_f16(acc[1][3], a1, __float_as_uint(v1.z), __float_as_uint(v1.w));
    }

    #pragma unroll
    for (int m = 0; m < 2; m++) {
        int rr = m * 16 + gr;
        #pragma unroll
        for (int j = 0; j < 4; j++) {
            int cA = n0 + j * 8 + 2 * gc;
            float b0 = bias[cA], b1 = bias[cA + 1];
            float v00 = lrelu(acc[m][j][0] + b0), v01 = lrelu(acc[m][j][1] + b1);
            float v10 = lrelu(acc[m][j][2] + b0), v11 = lrelu(acc[m][j][3] + b1);
            int wc = cA >> 1;
            outp[(rr    ) * outPitch + wc] = __uint_as_float(pack_h2(v00, v01));
            outp[(rr + 8) * outPitch + wc] = __uint_as_float(pack_h2(v10, v11));
        }
    }
}

__global__ __launch_bounds__(THREADS, 3)
void mlpac_kernel(
    const float* __restrict__ obs,
    const float* __restrict__ prop_W1, const float* __restrict__ prop_b1,
    const float* __restrict__ prop_b2,
    const float* __restrict__ ext_W1,  const float* __restrict__ ext_b1,
    const float* __restrict__ ext_b2,
    const float* __restrict__ opp_W1,  const float* __restrict__ opp_b1,
    const float* __restrict__ opp_b2,
    const float* __restrict__ pi_b1,   const float* __restrict__ pi_b2,
    const float* __restrict__ pi_b3,
    float* __restrict__ out)
{
    extern __shared__ float sm[];
    float* s_hid  = sm + HID_OFF;
    float* s_ef16 = sm + EF16_OFF;
    float* s_obs  = s_ef16;
    float* s_h1   = sm + HID_OFF;
    float* s_h2   = sm + EF16_OFF;

    const int tid  = threadIdx.x;
    const int warp = tid >> 5, lane = tid & 31;
    const int p    = blockIdx.y;
    const int b0   = blockIdx.x * TB;

    // ---------------- stage 0: obs ----------------
    for (int g = tid; g < TB * (OBSD / 4); g += THREADS) {
        int r = g / 12, q = g - r * 12;
        *(float4*)&s_obs[r * PE16W + q * 4] =
            *(const float4*)&obs[((size_t)(b0 + r) * NPLAYER + p) * OBSD + q * 4];
    }
    __syncthreads();

    // ---------------- stage 1a: hidden layers -> fp16 words (R13 coalesced form) ----------------
    for (int i = tid; i < 32 * 9 * 16; i += THREADS) {
        int r = i / 144, rest = i - r * 144, n = rest >> 4, jw = rest & 15;
        const float* w = prop_W1 + ((p * 9 + n) * 2) * 32 + 2 * jw;
        float o0 = s_obs[r * PE16W + 2 * n], o1 = s_obs[r * PE16W + 2 * n + 1];
        const float* bb = prop_b1 + (p * 9 + n) * 32 + 2 * jw;
        float v0 = lrelu(o0 * w[0] + o1 * w[32] + bb[0]);
        float v1 = lrelu(o0 * w[1] + o1 * w[33] + bb[1]);
        s_hid[r * PHIDW + n * 16 + jw] = __uint_as_float(pack_h2(v0, v1));
    }
    for (int i = tid; i < 32 * 2 * 16; i += THREADS) {
        int r = i >> 5, rest = i & 31, n = rest >> 4, jw = rest & 15;
        const float* w = ext_W1 + ((p * 2 + n) * 6) * 32 + 2 * jw;
        const float* bb = ext_b1 + (p * 2 + n) * 32 + 2 * jw;
        float v0 = bb[0], v1 = bb[1];
        #pragma unroll
        for (int q = 0; q < 6; q++) {
            float o = s_obs[r * PE16W + 18 + n * 6 + q];
            v0 += o * w[q * 32]; v1 += o * w[q * 32 + 1];
        }
        s_hid[r * PHIDW + 144 + n * 16 + jw] = __uint_as_float(pack_h2(lrelu(v0), lrelu(v1)));
    }
    for (int i = tid; i < 32 * 16; i += THREADS) {
        int r = i >> 4, jw = i & 15;
        const float* w = opp_W1 + (p * 18) * 32 + 2 * jw;
        const float* bb = opp_b1 + p * 32 + 2 * jw;
        float v0 = bb[0], v1 = bb[1];
        #pragma unroll
        for (int q = 0; q < 18; q++) {
            float o = s_obs[r * PE16W + 30 + q];
            v0 += o * w[q * 32]; v1 += o * w[q * 32 + 1];
        }
        s_hid[r * PHIDW + 176 + jw] = __uint_as_float(pack_h2(lrelu(v0), lrelu(v1)));
    }
    __syncthreads();

    // ---------------- stage 1b: enc (fused; ext/opp hoisted, branch-free) ----------------
    {
        unsigned aad0 = s2u(s_hid + (lane & 15) * PHIDW + ((lane >> 4) << 2));
        unsigned aad1 = s2u(s_hid + (16 + (lane & 15)) * PHIDW + ((lane >> 4) << 2));
        enc_all(prop_b2, ext_b2, opp_b2, s_ef16, aad0, aad1, warp, lane, p);
    }
    __syncthreads();

    // ---------------- stage 2: h1 = lrelu(enc @ pi_W1 + b1) ----------------
    pi_stage<36, PKP_PI1, PE16W>(pi_b1 + p * 256, s_ef16, s_h1, PH1W, warp, lane, p);
    __syncthreads();

    // ---------------- stage 3: h2 = lrelu(h1 @ pi_W2 + b2) ----------------
    pi_stage<16, PKP_PI2, PH1W>(pi_b2 + p * 256, s_h1, s_h2, PH1W, warp, lane, p);
    __syncthreads();

    // ---------------- stage 4: out = tanh(h2 @ pi_W3 + b3)  [1 warp, mma] ----------------
    if (warp == 0) {
        const int gr = lane >> 2, gc = lane & 3;
        const float4* pkw3 = g_pk4 + (size_t)p * PK_PLAYER + PKP_PI3;
        const unsigned aad0 = s2u(s_h2 + (lane & 15) * PH1W + ((lane >> 4) << 2));
        const unsigned aad1 = s2u(s_h2 + (16 + (lane & 15)) * PH1W + ((lane >> 4) << 2));
        float acc[2][4];
        #pragma unroll
        for (int m = 0; m < 2; m++)
            #pragma unroll
            for (int u = 0; u < 4; u++) acc[m][u] = 0.f;
        #pragma unroll
        for (int c = 0; c < 16; c++) {
            float4 v = pkw3[(c >> 1) * 32 + lane];
            unsigned b0 = __float_as_uint((c & 1) ? v.z : v.x);
            unsigned b1 = __float_as_uint((c & 1) ? v.w : v.y);
            unsigned a0[4], a1[4];
            LDSM4(a0, aad0 + c * 32);
            LDSM4(a1, aad1 + c * 32);
            mma_f16(acc[0], a0, b0, b1);
            mma_f16(acc[1], a1, b0, b1);
        }
        int c0 = 2 * gc, c1 = 2 * gc + 1;
        float bb0 = (c0 < 3) ? pi_b3[p * 3 + c0] : 0.f;
        float bb1 = (c1 < 3) ? pi_b3[p * 3 + c1] : 0.f;
        #pragma unroll
        for (int m = 0; m < 2; m++) {
            int r0 = m * 16 + gr, r1 = r0 + 8;
            if (c0 < 3) {
                out[((size_t)(b0 + r0) * NPLAYER + p) * 3 + c0] = tanhf(acc[m][0] + bb0);
                out[((size_t)(b0 + r1) * NPLAYER + p) * 3 + c0] = tanhf(acc[m][2] + bb0);
            }
            if (c1 < 3) {
                out[((size_t)(b0 + r0) * NPLAYER + p) * 3 + c1] = tanhf(acc[m][1] + bb1);
                out[((size_t)(b0 + r1) * NPLAYER + p) * 3 + c1] = tanhf(acc[m][3] + bb1);
            }
        }
    }
}

extern "C" void kernel_launch(void* const* d_in, const int* in_sizes, int n_in,
                              void* d_out, int out_size)
{
    (void)in_sizes; (void)n_in; (void)out_size;
    const float* obs     = (const float*)d_in[0];
    const float* prop_W1 = (const float*)d_in[1];
    const float* prop_b1 = (const float*)d_in[2];
    const float* prop_W2 = (const float*)d_in[3];
    const float* prop_b2 = (const float*)d_in[4];
    const float* ext_W1  = (const float*)d_in[5];
    const float* ext_b1  = (const float*)d_in[6];
    const float* ext_W2  = (const float*)d_in[7];
    const float* ext_b2  = (const float*)d_in[8];
    const float* opp_W1  = (const float*)d_in[9];
    const float* opp_b1  = (const float*)d_in[10];
    const float* opp_W2  = (const float*)d_in[11];
    const float* opp_b2  = (const float*)d_in[12];
    const float* pi_W1   = (const float*)d_in[13];
    const float* pi_b1   = (const float*)d_in[14];
    const float* pi_W2   = (const float*)d_in[15];
    const float* pi_b2   = (const float*)d_in[16];
    const float* pi_W3   = (const float*)d_in[17];
    const float* pi_b3   = (const float*)d_in[18];
    float* out = (float*)d_out;

    repack_kernel<<<(PK_TOTAL + 255) / 256, 256>>>(prop_W2, ext_W2, opp_W2,
                                                   pi_W1, pi_W2, pi_W3);

    const int smem_bytes = SMEM_WORDS * sizeof(float);
    cudaFuncSetAttribute(mlpac_kernel, cudaFuncAttributeMaxDynamicSharedMemorySize, smem_bytes);

    dim3 grid(BATCH / TB, NPLAYER);
    mlpac_kernel<<<grid, THREADS, smem_bytes>>>(
        obs, prop_W1, prop_b1, prop_b2,
        ext_W1, ext_b1, ext_b2,
        opp_W1, opp_b1, opp_b2,
        pi_b1, pi_b2, pi_b3, out);
}